// round 15
// baseline (speedup 1.0000x reference)
#include <cuda_runtime.h>
#include <cuda_bf16.h>
#include <cuda_fp16.h>
#include <cub/cub.cuh>
#include <cstdint>

#define ALPHA_F 10.0f
#define DELTA_F 0.0005f
#define SEED_OFF 8389          // delta * N for N=2^24 (seed only; exactness checked per query)
#define CHUNK 2048             // sorted positions per block
#define MARGIN 512             // window slack each side
#define WSZ (CHUNK + 2 * MARGIN)   // 3072 floats = 12KB per window array

// ---- scratch (device globals: allocation-free rule) ----
__device__ float2       g_cy[16777216];                 // 128 MB: (clamped, array) interleaved
__device__ unsigned int g_k24[16777216];                // fixed-point keys (sort in)
__device__ unsigned int g_k24s[16777216];               // sorted keys (run detection)
__device__ unsigned int g_idx_in[16777216];
__device__ unsigned int g_idx[16777216];
__device__ float        g_xs[16777216];
__device__ float        g_ys[16777216];
__device__ __half2      g_AB[16777216];                 // 64 MB, streamed
__device__ unsigned char g_temp[200u * 1024u * 1024u];
__device__ double       g_accum;

__global__ __launch_bounds__(256) void k_init(const float4* __restrict__ in4,
                                              const float4* __restrict__ arr4, int n4) {
    int t = blockIdx.x * blockDim.x + threadIdx.x;
    if (t == 0) g_accum = 0.0;
    if (t >= n4) return;
    float4 v = __ldg(&in4[t]);
    float4 a = __ldg(&arr4[t]);
    float c[4] = { fminf(fmaxf(v.x,0.0f),1.0f), fminf(fmaxf(v.y,0.0f),1.0f),
                   fminf(fmaxf(v.z,0.0f),1.0f), fminf(fmaxf(v.w,0.0f),1.0f) };
    float av[4] = { a.x, a.y, a.z, a.w };
    uint4 k;
    k.x = (unsigned int)fminf(c[0]*16777216.0f, 16777215.0f);
    k.y = (unsigned int)fminf(c[1]*16777216.0f, 16777215.0f);
    k.z = (unsigned int)fminf(c[2]*16777216.0f, 16777215.0f);
    k.w = (unsigned int)fminf(c[3]*16777216.0f, 16777215.0f);
    ((uint4*)g_k24)[t] = k;
    unsigned int i0 = (unsigned int)t * 4u;
    ((uint4*)g_idx_in)[t] = make_uint4(i0, i0+1, i0+2, i0+3);
    #pragma unroll
    for (int u = 0; u < 4; u++)
        g_cy[i0 + u] = make_float2(c[u], av[u]);
}

// gather (xs, ys) from interleaved cy via sorted idx; one random float2 load each
__global__ __launch_bounds__(256) void k_gather(int n4) {
    int t = blockIdx.x * blockDim.x + threadIdx.x;
    if (t >= n4) return;
    uint4 id = __ldg(&((const uint4*)g_idx)[t]);
    float2 p0 = __ldg(&g_cy[id.x]);
    float2 p1 = __ldg(&g_cy[id.y]);
    float2 p2 = __ldg(&g_cy[id.z]);
    float2 p3 = __ldg(&g_cy[id.w]);
    ((float4*)g_xs)[t] = make_float4(p0.x, p1.x, p2.x, p3.x);
    ((float4*)g_ys)[t] = make_float4(p0.y, p1.y, p2.y, p3.y);
}

// Repair u24 tie-runs to exact (float key, idx) lex order. One thread per run
// start; stable insertion sort over the run (idx already ascending from the
// stable radix sort, so strict-> comparisons preserve idx order among equals).
__global__ __launch_bounds__(256) void k_cleanup(int n) {
    int k = blockIdx.x * blockDim.x + threadIdx.x;
    if (k >= n) return;
    unsigned int me = __ldg(&g_k24s[k]);
    if (k > 0 && __ldg(&g_k24s[k - 1]) == me) return;   // not a run start
    if (k + 1 >= n || __ldg(&g_k24s[k + 1]) != me) return; // run length 1
    int e = k + 2;
    while (e < n && __ldg(&g_k24s[e]) == me) e++;
    for (int a = k + 1; a < e; a++) {
        float xv = g_xs[a]; float yv = g_ys[a]; unsigned int iv = g_idx[a];
        int b = a - 1;
        while (b >= k && g_xs[b] > xv) {
            g_xs[b+1] = g_xs[b]; g_ys[b+1] = g_ys[b]; g_idx[b+1] = g_idx[b];
            b--;
        }
        g_xs[b+1] = xv; g_ys[b+1] = yv; g_idx[b+1] = iv;
    }
}

// exact global fallback: full binary search over [0, n)  (rare)
__device__ __noinline__ float eval_global(float q, int n) {
    int lo = 0, hi = n;
    while (lo < hi) {
        int mid = (lo + hi) >> 1;
        if (__ldg(&g_xs[mid]) <= q) lo = mid + 1; else hi = mid;
    }
    int j = lo - 1;
    if (j < 0)      return __ldg(&g_ys[0]);
    if (j >= n - 1) return __ldg(&g_ys[n - 1]);
    float x0 = __ldg(&g_xs[j]), x1 = __ldg(&g_xs[j + 1]);
    float y0 = __ldg(&g_ys[j]), y1 = __ldg(&g_ys[j + 1]);
    return y0 + (q - x0) * (y1 - y0) / (x1 - x0);
}

// evaluate f(q) from staged window sx/sy = xs/ys[s0 .. s0+w)
__device__ __forceinline__ float eval_win(float q, const float* __restrict__ sx,
                                          const float* __restrict__ sy,
                                          int s0, int w, int n) {
    int lo = 0, hi = w;
    while (lo < hi) {
        int mid = (lo + hi) >> 1;
        if (sx[mid] <= q) lo = mid + 1; else hi = mid;
    }
    if (lo == 0) {
        if (s0 == 0) return sy[0];
        return eval_global(q, n);
    }
    if (lo == w) {
        if (s0 + w == n) return sy[w - 1];
        return eval_global(q, n);
    }
    float x0 = sx[lo - 1], x1 = sx[lo];
    float y0 = sy[lo - 1], y1 = sy[lo];
    return y0 + (q - x0) * (y1 - y0) / (x1 - x0);
}

__global__ __launch_bounds__(256) void k_interp(int n) {
    __shared__ float sx[WSZ], sy[WSZ];     // 24 KB -> 8 blocks/SM

    const int K = blockIdx.x * CHUNK;
    const int base = K + threadIdx.x * 8;
    const int m = (base < n) ? ((n - base < 8) ? (n - base) : 8) : 0;

    float xk[8];
    unsigned int oidx[8];
    if (m == 8) {
        float4 a = __ldg((const float4*)&g_xs[base]);
        float4 b = __ldg((const float4*)&g_xs[base + 4]);
        xk[0]=a.x; xk[1]=a.y; xk[2]=a.z; xk[3]=a.w;
        xk[4]=b.x; xk[5]=b.y; xk[6]=b.z; xk[7]=b.w;
        uint4 ia = __ldcs((const uint4*)&g_idx[base]);
        uint4 ib = __ldcs((const uint4*)&g_idx[base + 4]);
        oidx[0]=ia.x; oidx[1]=ia.y; oidx[2]=ia.z; oidx[3]=ia.w;
        oidx[4]=ib.x; oidx[5]=ib.y; oidx[6]=ib.z; oidx[7]=ib.w;
    } else {
        for (int t = 0; t < 8; t++) {
            xk[t]  = (t < m) ? __ldg(&g_xs[base + t]) : 0.0f;
            oidx[t] = (t < m) ? __ldcs(&g_idx[base + t]) : 0u;
        }
    }

    // ---------------- phase A: window around K + SEED_OFF ----------------
    int sa = K + SEED_OFF - MARGIN;
    if (sa > n - WSZ) sa = n - WSZ;
    if (sa < 0) sa = 0;
    sa &= ~3;
    int wa = min(WSZ, n - sa);
    {
        int w4 = (wa + 3) >> 2;
        const float4* x4 = (const float4*)(g_xs + sa);
        const float4* y4 = (const float4*)(g_ys + sa);
        for (int i = threadIdx.x; i < w4; i += 256) {
            ((float4*)sx)[i] = __ldg(&x4[i]);
            ((float4*)sy)[i] = __ldg(&y4[i]);
        }
    }
    __syncthreads();

    float A[8];
    #pragma unroll
    for (int t = 0; t < 8; t++)
        if (t < m) A[t] = eval_win(xk[t] + DELTA_F, sx, sy, sa, wa, n);
    __syncthreads();                        // everyone done reading before restage

    // ---------------- phase B: window around K - SEED_OFF ----------------
    int sb = K - SEED_OFF - MARGIN;
    if (sb > n - WSZ) sb = n - WSZ;
    if (sb < 0) sb = 0;
    sb &= ~3;
    int wb = min(WSZ, n - sb);
    {
        int w4 = (wb + 3) >> 2;
        const float4* x4 = (const float4*)(g_xs + sb);
        const float4* y4 = (const float4*)(g_ys + sb);
        for (int i = threadIdx.x; i < w4; i += 256) {
            ((float4*)sx)[i] = __ldg(&x4[i]);
            ((float4*)sy)[i] = __ldg(&y4[i]);
        }
    }
    __syncthreads();

    #pragma unroll
    for (int t = 0; t < 8; t++) {
        if (t >= m) break;
        float B = eval_win(xk[t] - DELTA_F, sx, sy, sb, wb, n);
        __stcs(&g_AB[oidx[t]], __floats2half2_rn(A[t], B));
    }
}

// gap_i = relu(A_i - B_{i+1}); streamed half2 reads, 4 gaps per thread
__global__ __launch_bounds__(256) void k_gap(int n) {
    float acc = 0.0f;
    int stride = gridDim.x * blockDim.x;
    for (int t = blockIdx.x * blockDim.x + threadIdx.x; 4 * t < n - 1; t += stride) {
        int i = 4 * t;
        uint4 u = __ldcs((const uint4*)&g_AB[i]);
        __half2 h0 = *(__half2*)&u.x;
        __half2 h1 = *(__half2*)&u.y;
        __half2 h2 = *(__half2*)&u.z;
        __half2 h3 = *(__half2*)&u.w;
        acc += fmaxf(__low2float(h0) - __high2float(h1), 0.0f);
        acc += fmaxf(__low2float(h1) - __high2float(h2), 0.0f);
        acc += fmaxf(__low2float(h2) - __high2float(h3), 0.0f);
        if (i + 4 < n) {
            __half2 h4 = g_AB[i + 4];
            acc += fmaxf(__low2float(h3) - __high2float(h4), 0.0f);
        }
    }
    typedef cub::BlockReduce<float, 256> BR;
    __shared__ typename BR::TempStorage ts;
    float s = BR(ts).Sum(acc);
    if (threadIdx.x == 0) atomicAdd(&g_accum, (double)s);
}

__global__ void k_final(float* __restrict__ out) {
    out[0] = (float)((double)ALPHA_F * g_accum);
}

extern "C" void kernel_launch(void* const* d_in, const int* in_sizes, int n_in,
                              void* d_out, int out_size) {
    const float* indices = (const float*)d_in[0];
    const float* array   = (const float*)d_in[1];
    int n = in_sizes[0];

    unsigned int* p_k24 = nullptr;
    unsigned int* p_k24s = nullptr;
    unsigned int* p_idx_in = nullptr;
    unsigned int* p_idx = nullptr;
    void* p_temp = nullptr;
    cudaGetSymbolAddress((void**)&p_k24, g_k24);
    cudaGetSymbolAddress((void**)&p_k24s, g_k24s);
    cudaGetSymbolAddress((void**)&p_idx_in, g_idx_in);
    cudaGetSymbolAddress((void**)&p_idx, g_idx);
    cudaGetSymbolAddress(&p_temp, g_temp);

    const int threads = 256;
    int n4 = n / 4;
    int b4 = (n4 + threads - 1) / threads;
    int b1 = (n + threads - 1) / threads;

    // 1) clamp + fixed-point keys + iota + interleaved (c,y) + zero accum
    k_init<<<b4, threads>>>((const float4*)indices, (const float4*)array, n4);

    // 2) stable sort on 24-bit fixed-point keys -> 3 onesweep passes
    size_t temp_bytes = sizeof(g_temp);
    cub::DeviceRadixSort::SortPairs(p_temp, temp_bytes,
                                    p_k24, p_k24s,
                                    p_idx_in, p_idx,
                                    n, 0, 24);

    // 3) gather (xs, ys) from interleaved cy
    k_gather<<<b4, threads>>>(n4);

    // 4) repair u24 tie-runs to exact (key, idx) order
    k_cleanup<<<b1, threads>>>(n);

    // 5) two-phase block-windowed smem interpolation, streaming half2 scatter
    int iblocks = (n + CHUNK - 1) / CHUNK;
    k_interp<<<iblocks, threads>>>(n);

    // 6) gap + reduction
    k_gap<<<592, threads>>>(n);

    // 7) scale + write scalar output
    k_final<<<1, 1>>>((float*)d_out);
}

// round 16
// speedup vs baseline: 1.1602x; 1.1602x over previous
#include <cuda_runtime.h>
#include <cuda_bf16.h>
#include <cuda_fp16.h>
#include <cub/cub.cuh>
#include <cstdint>

#define ALPHA_F 10.0f
#define DELTA_F 0.0005f
#define SEED_OFF 8389          // delta * N for N=2^24 (seed only; exactness checked per query)
#define CHUNK 2048             // sorted positions per block
#define MARGIN 512             // window slack each side
#define WSZ (CHUNK + 2 * MARGIN)   // 3072 floats = 12KB per window array

// ---- scratch (device globals: allocation-free rule) ----
__device__ float2       g_cy[16777216];                 // 128 MB: (clamped, array) pairs
__device__ float        g_keys[16777216];               // u24 key disguised as float bits
__device__ float        g_keys_s[16777216];             // sorted keys (content unused)
__device__ unsigned int g_idx_in[16777216];
__device__ unsigned int g_idx[16777216];
__device__ float        g_xs[16777216];
__device__ float        g_ys[16777216];
__device__ __half2      g_AB[16777216];                 // 64 MB, streamed
__device__ unsigned char g_temp[200u * 1024u * 1024u];
__device__ double       g_accum;

__device__ __forceinline__ unsigned int key24_of(float c) {
    return (unsigned int)fminf(c * 16777216.0f, 16777215.0f);
}

__global__ __launch_bounds__(256) void k_init(const float4* __restrict__ in4,
                                              const float4* __restrict__ arr4, int n4) {
    int t = blockIdx.x * blockDim.x + threadIdx.x;
    if (t == 0) g_accum = 0.0;
    if (t >= n4) return;
    float4 v = __ldg(&in4[t]);
    float4 a = __ldg(&arr4[t]);
    float c[4] = { fminf(fmaxf(v.x,0.0f),1.0f), fminf(fmaxf(v.y,0.0f),1.0f),
                   fminf(fmaxf(v.z,0.0f),1.0f), fminf(fmaxf(v.w,0.0f),1.0f) };
    // u24 fixed-point key stored as a (denormal) float bit pattern: CUB's
    // float transform sets the sign bit for non-negatives, so transformed
    // bits [0,24) == k24 and bits [24,32) are constant -> end_bit=24 is exact.
    float4 kf;
    kf.x = __uint_as_float(key24_of(c[0]));
    kf.y = __uint_as_float(key24_of(c[1]));
    kf.z = __uint_as_float(key24_of(c[2]));
    kf.w = __uint_as_float(key24_of(c[3]));
    ((float4*)g_keys)[t] = kf;
    unsigned int i0 = (unsigned int)t * 4u;
    ((uint4*)g_idx_in)[t] = make_uint4(i0, i0+1, i0+2, i0+3);
    __stcs(&g_cy[i0+0], make_float2(c[0], a.x));
    __stcs(&g_cy[i0+1], make_float2(c[1], a.y));
    __stcs(&g_cy[i0+2], make_float2(c[2], a.z));
    __stcs(&g_cy[i0+3], make_float2(c[3], a.w));
}

// gather (xs, ys) from interleaved cy via sorted idx; one random float2 load each
__global__ __launch_bounds__(256) void k_gather(int n4) {
    int t = blockIdx.x * blockDim.x + threadIdx.x;
    if (t >= n4) return;
    uint4 id = __ldg(&((const uint4*)g_idx)[t]);
    float2 p0 = __ldg(&g_cy[id.x]);
    float2 p1 = __ldg(&g_cy[id.y]);
    float2 p2 = __ldg(&g_cy[id.z]);
    float2 p3 = __ldg(&g_cy[id.w]);
    ((float4*)g_xs)[t] = make_float4(p0.x, p1.x, p2.x, p3.x);
    ((float4*)g_ys)[t] = make_float4(p0.y, p1.y, p2.y, p3.y);
}

// Repair u24 tie-runs to exact (float key, idx) lex order. Runs detected by
// recomputing k24 from xs (identical expression to k_init -> identical value;
// run contents share one k24, so concurrent in-run permutation cannot change
// detection). One owner thread per run start; strict-compare insertion sort
// preserves idx order among exactly-equal floats (stable).
__global__ __launch_bounds__(256) void k_cleanup(int n) {
    int k = blockIdx.x * blockDim.x + threadIdx.x;
    if (k >= n) return;
    unsigned int me = key24_of(g_xs[k]);
    if (k > 0 && key24_of(g_xs[k - 1]) == me) return;       // not a run start
    if (k + 1 >= n || key24_of(g_xs[k + 1]) != me) return;  // run length 1
    int e = k + 2;
    while (e < n && key24_of(g_xs[e]) == me) e++;
    for (int a = k + 1; a < e; a++) {
        float xv = g_xs[a]; float yv = g_ys[a]; unsigned int iv = g_idx[a];
        int b = a - 1;
        while (b >= k && g_xs[b] > xv) {
            g_xs[b+1] = g_xs[b]; g_ys[b+1] = g_ys[b]; g_idx[b+1] = g_idx[b];
            b--;
        }
        g_xs[b+1] = xv; g_ys[b+1] = yv; g_idx[b+1] = iv;
    }
}

// exact global fallback: full binary search over [0, n)  (rare)
__device__ __noinline__ float eval_global(float q, int n) {
    int lo = 0, hi = n;
    while (lo < hi) {
        int mid = (lo + hi) >> 1;
        if (__ldg(&g_xs[mid]) <= q) lo = mid + 1; else hi = mid;
    }
    int j = lo - 1;
    if (j < 0)      return __ldg(&g_ys[0]);
    if (j >= n - 1) return __ldg(&g_ys[n - 1]);
    float x0 = __ldg(&g_xs[j]), x1 = __ldg(&g_xs[j + 1]);
    float y0 = __ldg(&g_ys[j]), y1 = __ldg(&g_ys[j + 1]);
    return y0 + (q - x0) * (y1 - y0) / (x1 - x0);
}

// evaluate f(q) from staged window sx/sy = xs/ys[s0 .. s0+w)
__device__ __forceinline__ float eval_win(float q, const float* __restrict__ sx,
                                          const float* __restrict__ sy,
                                          int s0, int w, int n) {
    int lo = 0, hi = w;
    while (lo < hi) {
        int mid = (lo + hi) >> 1;
        if (sx[mid] <= q) lo = mid + 1; else hi = mid;
    }
    if (lo == 0) {
        if (s0 == 0) return sy[0];                 // q < xs[0] -> left fill
        return eval_global(q, n);
    }
    if (lo == w) {
        if (s0 + w == n) return sy[w - 1];         // q >= xs[n-1] -> right fill
        return eval_global(q, n);
    }
    float x0 = sx[lo - 1], x1 = sx[lo];
    float y0 = sy[lo - 1], y1 = sy[lo];
    return y0 + (q - x0) * (y1 - y0) / (x1 - x0);  // x1 > q >= x0
}

__global__ __launch_bounds__(256) void k_interp(int n) {
    __shared__ float sxa[WSZ], sya[WSZ], sxb[WSZ], syb[WSZ];

    const int K = blockIdx.x * CHUNK;
    if (K >= n) return;

    int sa = K + SEED_OFF - MARGIN;
    if (sa > n - WSZ) sa = n - WSZ;
    if (sa < 0) sa = 0;
    sa &= ~3;
    int wa = min(WSZ, n - sa);

    int sb = K - SEED_OFF - MARGIN;
    if (sb > n - WSZ) sb = n - WSZ;
    if (sb < 0) sb = 0;
    sb &= ~3;
    int wb = min(WSZ, n - sb);

    {
        int wa4 = (wa + 3) >> 2, wb4 = (wb + 3) >> 2;
        const float4* xa4 = (const float4*)(g_xs + sa);
        const float4* ya4 = (const float4*)(g_ys + sa);
        const float4* xb4 = (const float4*)(g_xs + sb);
        const float4* yb4 = (const float4*)(g_ys + sb);
        for (int i = threadIdx.x; i < wa4; i += 256) {
            ((float4*)sxa)[i] = __ldg(&xa4[i]);
            ((float4*)sya)[i] = __ldg(&ya4[i]);
        }
        for (int i = threadIdx.x; i < wb4; i += 256) {
            ((float4*)sxb)[i] = __ldg(&xb4[i]);
            ((float4*)syb)[i] = __ldg(&yb4[i]);
        }
    }
    __syncthreads();

    const int base = K + threadIdx.x * 8;
    if (base >= n) return;
    const int m = (n - base < 8) ? (n - base) : 8;

    float xk[8];
    if (m == 8) {
        float4 a = __ldg((const float4*)&g_xs[base]);
        float4 b = __ldg((const float4*)&g_xs[base + 4]);
        xk[0]=a.x; xk[1]=a.y; xk[2]=a.z; xk[3]=a.w;
        xk[4]=b.x; xk[5]=b.y; xk[6]=b.z; xk[7]=b.w;
    } else {
        for (int t = 0; t < 8; t++) xk[t] = (t < m) ? __ldg(&g_xs[base + t]) : 0.0f;
    }

    unsigned int oidx[8];
    if (m == 8) {
        uint4 a = __ldcs((const uint4*)&g_idx[base]);
        uint4 b = __ldcs((const uint4*)&g_idx[base + 4]);
        oidx[0]=a.x; oidx[1]=a.y; oidx[2]=a.z; oidx[3]=a.w;
        oidx[4]=b.x; oidx[5]=b.y; oidx[6]=b.z; oidx[7]=b.w;
    } else {
        for (int t = 0; t < m; t++) oidx[t] = __ldcs(&g_idx[base + t]);
    }

    #pragma unroll
    for (int t = 0; t < 8; t++) {
        if (t >= m) break;
        float A = eval_win(xk[t] + DELTA_F, sxa, sya, sa, wa, n);
        float B = eval_win(xk[t] - DELTA_F, sxb, syb, sb, wb, n);
        __stcs(&g_AB[oidx[t]], __floats2half2_rn(A, B));
    }
}

// gap_i = relu(A_i - B_{i+1}); streamed half2 reads, 4 gaps per thread
__global__ __launch_bounds__(256) void k_gap(int n) {
    float acc = 0.0f;
    int stride = gridDim.x * blockDim.x;
    for (int t = blockIdx.x * blockDim.x + threadIdx.x; 4 * t < n - 1; t += stride) {
        int i = 4 * t;
        uint4 u = __ldcs((const uint4*)&g_AB[i]);
        __half2 h0 = *(__half2*)&u.x;
        __half2 h1 = *(__half2*)&u.y;
        __half2 h2 = *(__half2*)&u.z;
        __half2 h3 = *(__half2*)&u.w;
        acc += fmaxf(__low2float(h0) - __high2float(h1), 0.0f);
        acc += fmaxf(__low2float(h1) - __high2float(h2), 0.0f);
        acc += fmaxf(__low2float(h2) - __high2float(h3), 0.0f);
        if (i + 4 < n) {
            __half2 h4 = g_AB[i + 4];
            acc += fmaxf(__low2float(h3) - __high2float(h4), 0.0f);
        }
    }
    typedef cub::BlockReduce<float, 256> BR;
    __shared__ typename BR::TempStorage ts;
    float s = BR(ts).Sum(acc);
    if (threadIdx.x == 0) atomicAdd(&g_accum, (double)s);
}

__global__ void k_final(float* __restrict__ out) {
    out[0] = (float)((double)ALPHA_F * g_accum);
}

extern "C" void kernel_launch(void* const* d_in, const int* in_sizes, int n_in,
                              void* d_out, int out_size) {
    const float* indices = (const float*)d_in[0];
    const float* array   = (const float*)d_in[1];
    int n = in_sizes[0];

    float* p_keys = nullptr;
    float* p_keys_s = nullptr;
    unsigned int* p_idx_in = nullptr;
    unsigned int* p_idx = nullptr;
    void* p_temp = nullptr;
    cudaGetSymbolAddress((void**)&p_keys, g_keys);
    cudaGetSymbolAddress((void**)&p_keys_s, g_keys_s);
    cudaGetSymbolAddress((void**)&p_idx_in, g_idx_in);
    cudaGetSymbolAddress((void**)&p_idx, g_idx);
    cudaGetSymbolAddress(&p_temp, g_temp);

    const int threads = 256;
    int n4 = n / 4;
    int b4 = (n4 + threads - 1) / threads;
    int b1 = (n + threads - 1) / threads;

    // 1) clamp + disguised u24 keys + iota + interleaved (c,y) + zero accum
    k_init<<<b4, threads>>>((const float4*)indices, (const float4*)array, n4);

    // 2) stable sort, float policy, 3 passes (end_bit=24 on disguised keys)
    size_t temp_bytes = sizeof(g_temp);
    cub::DeviceRadixSort::SortPairs(p_temp, temp_bytes,
                                    p_keys, p_keys_s,
                                    p_idx_in, p_idx,
                                    n, 0, 24);

    // 3) gather (xs, ys) from interleaved cy      [profiled launch #6]
    k_gather<<<b4, threads>>>(n4);

    // 4) repair u24 tie-runs to exact (key, idx) order
    k_cleanup<<<b1, threads>>>(n);

    // 5) block-windowed smem interpolation, streaming half2 scatter
    int iblocks = (n + CHUNK - 1) / CHUNK;
    k_interp<<<iblocks, threads>>>(n);

    // 6) gap + reduction
    k_gap<<<592, threads>>>(n);

    // 7) scale + write scalar output
    k_final<<<1, 1>>>((float*)d_out);
}

// round 17
// speedup vs baseline: 1.2561x; 1.0827x over previous
#include <cuda_runtime.h>
#include <cuda_bf16.h>
#include <cuda_fp16.h>
#include <cub/cub.cuh>
#include <cstdint>

#define ALPHA_F 10.0f
#define DELTA_F 0.0005f
#define SEED_OFF 8389          // delta * N for N=2^24 (seed only; exactness checked per query)
#define CHUNK 2048             // sorted positions per block
#define MARGIN 512             // window slack each side
#define WSZ (CHUNK + 2 * MARGIN)   // 3072 floats = 12KB per window array

// ---- scratch (device globals: allocation-free rule) ----
__device__ float        g_keys[16777216];               // u24 key disguised as float bits
__device__ float        g_keys_s[16777216];             // sorted disguised keys (run detect)
__device__ unsigned int g_idx_in[16777216];
__device__ unsigned int g_idx[16777216];
__device__ float        g_xs[16777216];
__device__ float        g_ys[16777216];
__device__ __half2      g_AB[16777216];                 // 64 MB, streamed
__device__ unsigned char g_temp[200u * 1024u * 1024u];
__device__ double       g_accum;

__device__ __forceinline__ float clamp01(float v) {
    return fminf(fmaxf(v, 0.0f), 1.0f);
}
__device__ __forceinline__ unsigned int key24_of(float c) {
    return (unsigned int)fminf(c * 16777216.0f, 16777215.0f);
}

__global__ __launch_bounds__(256) void k_init(const float4* __restrict__ in4, int n4) {
    int t = blockIdx.x * blockDim.x + threadIdx.x;
    if (t == 0) g_accum = 0.0;
    if (t >= n4) return;
    float4 v = __ldg(&in4[t]);
    // u24 fixed-point key of clamp(x), stored as a (denormal) float bit
    // pattern: CUB's float ascending transform sets the sign bit for
    // non-negative patterns, so transformed bits [0,24) == k24 and bits
    // [24,32) are constant -> end_bit=24 sorts exactly by k24, stable.
    float4 kf;
    kf.x = __uint_as_float(key24_of(clamp01(v.x)));
    kf.y = __uint_as_float(key24_of(clamp01(v.y)));
    kf.z = __uint_as_float(key24_of(clamp01(v.z)));
    kf.w = __uint_as_float(key24_of(clamp01(v.w)));
    ((float4*)g_keys)[t] = kf;
    unsigned int i0 = (unsigned int)t * 4u;
    ((uint4*)g_idx_in)[t] = make_uint4(i0, i0 + 1, i0 + 2, i0 + 3);
}

// xs[k] = clamp(indices[idx[k]]): random reads from ONE 64MB array ->
// full permutation reuse in L2 (effective traffic ~= 64MB, the R14 lesson)
__global__ __launch_bounds__(256) void k_gather_x(const float* __restrict__ indices, int n4) {
    int t = blockIdx.x * blockDim.x + threadIdx.x;
    if (t >= n4) return;
    uint4 id = __ldg(&((const uint4*)g_idx)[t]);
    float4 x;
    x.x = clamp01(__ldg(&indices[id.x]));
    x.y = clamp01(__ldg(&indices[id.y]));
    x.z = clamp01(__ldg(&indices[id.z]));
    x.w = clamp01(__ldg(&indices[id.w]));
    ((float4*)g_xs)[t] = x;
}

// Repair u24 tie-runs to exact (clamped key, idx) lex order. Runs detected
// on the sorted disguised keys (coalesced, never modified). One owner thread
// per run start; strict-compare insertion sort on xs keeps idx order among
// exactly-equal floats (stable). Runs after gather_x, before gather_y, so ys
// needs no repair.
__global__ __launch_bounds__(256) void k_cleanup(int n) {
    int k = blockIdx.x * blockDim.x + threadIdx.x;
    if (k >= n) return;
    unsigned int me = __float_as_uint(g_keys_s[k]);
    if (k > 0 && __float_as_uint(g_keys_s[k - 1]) == me) return;       // not run start
    if (k + 1 >= n || __float_as_uint(g_keys_s[k + 1]) != me) return;  // run len 1
    int e = k + 2;
    while (e < n && __float_as_uint(g_keys_s[e]) == me) e++;
    for (int a = k + 1; a < e; a++) {
        float xv = g_xs[a]; unsigned int iv = g_idx[a];
        int b = a - 1;
        while (b >= k && g_xs[b] > xv) {
            g_xs[b + 1] = g_xs[b]; g_idx[b + 1] = g_idx[b];
            b--;
        }
        g_xs[b + 1] = xv; g_idx[b + 1] = iv;
    }
}

// ys[k] = array[idx[k]] (idx final): second 64MB-array gather, clean L2 reuse
__global__ __launch_bounds__(256) void k_gather_y(const float* __restrict__ array, int n4) {
    int t = blockIdx.x * blockDim.x + threadIdx.x;
    if (t >= n4) return;
    uint4 id = __ldg(&((const uint4*)g_idx)[t]);
    float4 y;
    y.x = __ldg(&array[id.x]);
    y.y = __ldg(&array[id.y]);
    y.z = __ldg(&array[id.z]);
    y.w = __ldg(&array[id.w]);
    ((float4*)g_ys)[t] = y;
}

// exact global fallback: full binary search over [0, n)  (rare)
__device__ __noinline__ float eval_global(float q, int n) {
    int lo = 0, hi = n;
    while (lo < hi) {
        int mid = (lo + hi) >> 1;
        if (__ldg(&g_xs[mid]) <= q) lo = mid + 1; else hi = mid;
    }
    int j = lo - 1;
    if (j < 0)      return __ldg(&g_ys[0]);
    if (j >= n - 1) return __ldg(&g_ys[n - 1]);
    float x0 = __ldg(&g_xs[j]), x1 = __ldg(&g_xs[j + 1]);
    float y0 = __ldg(&g_ys[j]), y1 = __ldg(&g_ys[j + 1]);
    return y0 + (q - x0) * (y1 - y0) / (x1 - x0);
}

// evaluate f(q) from staged window sx/sy = xs/ys[s0 .. s0+w)
__device__ __forceinline__ float eval_win(float q, const float* __restrict__ sx,
                                          const float* __restrict__ sy,
                                          int s0, int w, int n) {
    int lo = 0, hi = w;
    while (lo < hi) {
        int mid = (lo + hi) >> 1;
        if (sx[mid] <= q) lo = mid + 1; else hi = mid;
    }
    if (lo == 0) {
        if (s0 == 0) return sy[0];                 // q < xs[0] -> left fill
        return eval_global(q, n);
    }
    if (lo == w) {
        if (s0 + w == n) return sy[w - 1];         // q >= xs[n-1] -> right fill
        return eval_global(q, n);
    }
    float x0 = sx[lo - 1], x1 = sx[lo];
    float y0 = sy[lo - 1], y1 = sy[lo];
    return y0 + (q - x0) * (y1 - y0) / (x1 - x0);  // x1 > q >= x0
}

__global__ __launch_bounds__(256) void k_interp(int n) {
    __shared__ float sxa[WSZ], sya[WSZ], sxb[WSZ], syb[WSZ];

    const int K = blockIdx.x * CHUNK;
    if (K >= n) return;

    int sa = K + SEED_OFF - MARGIN;
    if (sa > n - WSZ) sa = n - WSZ;
    if (sa < 0) sa = 0;
    sa &= ~3;
    int wa = min(WSZ, n - sa);

    int sb = K - SEED_OFF - MARGIN;
    if (sb > n - WSZ) sb = n - WSZ;
    if (sb < 0) sb = 0;
    sb &= ~3;
    int wb = min(WSZ, n - sb);

    {
        int wa4 = (wa + 3) >> 2, wb4 = (wb + 3) >> 2;
        const float4* xa4 = (const float4*)(g_xs + sa);
        const float4* ya4 = (const float4*)(g_ys + sa);
        const float4* xb4 = (const float4*)(g_xs + sb);
        const float4* yb4 = (const float4*)(g_ys + sb);
        for (int i = threadIdx.x; i < wa4; i += 256) {
            ((float4*)sxa)[i] = __ldg(&xa4[i]);
            ((float4*)sya)[i] = __ldg(&ya4[i]);
        }
        for (int i = threadIdx.x; i < wb4; i += 256) {
            ((float4*)sxb)[i] = __ldg(&xb4[i]);
            ((float4*)syb)[i] = __ldg(&yb4[i]);
        }
    }
    __syncthreads();

    const int base = K + threadIdx.x * 8;
    if (base >= n) return;
    const int m = (n - base < 8) ? (n - base) : 8;

    float xk[8];
    if (m == 8) {
        float4 a = __ldg((const float4*)&g_xs[base]);
        float4 b = __ldg((const float4*)&g_xs[base + 4]);
        xk[0]=a.x; xk[1]=a.y; xk[2]=a.z; xk[3]=a.w;
        xk[4]=b.x; xk[5]=b.y; xk[6]=b.z; xk[7]=b.w;
    } else {
        for (int t = 0; t < 8; t++) xk[t] = (t < m) ? __ldg(&g_xs[base + t]) : 0.0f;
    }

    unsigned int oidx[8];
    if (m == 8) {
        uint4 a = __ldcs((const uint4*)&g_idx[base]);
        uint4 b = __ldcs((const uint4*)&g_idx[base + 4]);
        oidx[0]=a.x; oidx[1]=a.y; oidx[2]=a.z; oidx[3]=a.w;
        oidx[4]=b.x; oidx[5]=b.y; oidx[6]=b.z; oidx[7]=b.w;
    } else {
        for (int t = 0; t < m; t++) oidx[t] = __ldcs(&g_idx[base + t]);
    }

    #pragma unroll
    for (int t = 0; t < 8; t++) {
        if (t >= m) break;
        float A = eval_win(xk[t] + DELTA_F, sxa, sya, sa, wa, n);
        float B = eval_win(xk[t] - DELTA_F, sxb, syb, sb, wb, n);
        __stcs(&g_AB[oidx[t]], __floats2half2_rn(A, B));
    }
}

// gap_i = relu(A_i - B_{i+1}); streamed half2 reads, 4 gaps per thread
__global__ __launch_bounds__(256) void k_gap(int n) {
    float acc = 0.0f;
    int stride = gridDim.x * blockDim.x;
    for (int t = blockIdx.x * blockDim.x + threadIdx.x; 4 * t < n - 1; t += stride) {
        int i = 4 * t;
        uint4 u = __ldcs((const uint4*)&g_AB[i]);
        __half2 h0 = *(__half2*)&u.x;
        __half2 h1 = *(__half2*)&u.y;
        __half2 h2 = *(__half2*)&u.z;
        __half2 h3 = *(__half2*)&u.w;
        acc += fmaxf(__low2float(h0) - __high2float(h1), 0.0f);
        acc += fmaxf(__low2float(h1) - __high2float(h2), 0.0f);
        acc += fmaxf(__low2float(h2) - __high2float(h3), 0.0f);
        if (i + 4 < n) {
            __half2 h4 = g_AB[i + 4];
            acc += fmaxf(__low2float(h3) - __high2float(h4), 0.0f);
        }
    }
    typedef cub::BlockReduce<float, 256> BR;
    __shared__ typename BR::TempStorage ts;
    float s = BR(ts).Sum(acc);
    if (threadIdx.x == 0) atomicAdd(&g_accum, (double)s);
}

__global__ void k_final(float* __restrict__ out) {
    out[0] = (float)((double)ALPHA_F * g_accum);
}

extern "C" void kernel_launch(void* const* d_in, const int* in_sizes, int n_in,
                              void* d_out, int out_size) {
    const float* indices = (const float*)d_in[0];
    const float* array   = (const float*)d_in[1];
    int n = in_sizes[0];

    float* p_keys = nullptr;
    float* p_keys_s = nullptr;
    unsigned int* p_idx_in = nullptr;
    unsigned int* p_idx = nullptr;
    void* p_temp = nullptr;
    cudaGetSymbolAddress((void**)&p_keys, g_keys);
    cudaGetSymbolAddress((void**)&p_keys_s, g_keys_s);
    cudaGetSymbolAddress((void**)&p_idx_in, g_idx_in);
    cudaGetSymbolAddress((void**)&p_idx, g_idx);
    cudaGetSymbolAddress(&p_temp, g_temp);

    const int threads = 256;
    int n4 = n / 4;
    int b4 = (n4 + threads - 1) / threads;
    int b1 = (n + threads - 1) / threads;

    // 1) disguised u24 keys + iota + zero accum (no extra data arrays)
    k_init<<<b4, threads>>>((const float4*)indices, n4);

    // 2) stable sort, float policy, 3 passes (end_bit=24 on disguised keys)
    size_t temp_bytes = sizeof(g_temp);
    cub::DeviceRadixSort::SortPairs(p_temp, temp_bytes,
                                    p_keys, p_keys_s,
                                    p_idx_in, p_idx,
                                    n, 0, 24);

    // 3) gather xs from the 64MB input (L2 permutation reuse)
    k_gather_x<<<b4, threads>>>(indices, n4);

    // 4) repair u24 tie-runs on (xs, idx) to exact lex order
    k_cleanup<<<b1, threads>>>(n);

    // 5) gather ys with the repaired idx (second 64MB-array gather)
    k_gather_y<<<b4, threads>>>(array, n4);

    // 6) block-windowed smem interpolation, streaming half2 scatter
    int iblocks = (n + CHUNK - 1) / CHUNK;
    k_interp<<<iblocks, threads>>>(n);

    // 7) gap + reduction
    k_gap<<<592, threads>>>(n);

    // 8) scale + write scalar output
    k_final<<<1, 1>>>((float*)d_out);
}